// round 15
// baseline (speedup 1.0000x reference)
#include <cuda_runtime.h>
#include <cuda_fp16.h>
#include <math.h>

#define LD 512
#define NB 32
#define NBLD (NB*LD)
#define TILE_B 16384          // bytes per 128x64 fp16 tile (BK=64)
#define S2 (2*TILE_B)         // bytes per pipeline stage (2 tiles)

// ---------------- scratch (declared as float for 16B-safe alignment) --------
__device__ float g_S_raw [(size_t)NB*LD*LD/2];  // E_row fp16
__device__ float g_ST_raw[(size_t)NB*LD*LD/2];  // E_col fp16
__device__ float g_Di_raw[(size_t)NB*LD*LD/2];  // D_i = |i - wj| fp16
__device__ float g_Dj_raw[(size_t)NB*LD*LD/2];  // D_j = |j - wi| fp16
__device__ float g_ih_raw[(size_t)NB*LD*LD/2];  // I fp16 row-major
__device__ float g_jh_raw[(size_t)NB*LD*LD/2];  // J fp16 row-major
__device__ float g_iT_raw[(size_t)NB*LD*LD/2];  // I^T fp16
__device__ float g_jT_raw[(size_t)NB*LD*LD/2];  // J^T fp16
__device__ float g_wT_raw[(size_t)LD*LD/2];     // W^T fp16
#define g_S  ((__half*)g_S_raw)
#define g_ST ((__half*)g_ST_raw)
#define g_Di ((__half*)g_Di_raw)
#define g_Dj ((__half*)g_Dj_raw)
#define g_ih ((__half*)g_ih_raw)
#define g_jh ((__half*)g_jh_raw)
#define g_iT ((__half*)g_iT_raw)
#define g_jT ((__half*)g_jT_raw)
#define g_wT ((__half*)g_wT_raw)
__device__ float g_prm[NB*4*LD], g_prs[NB*4*LD];
__device__ float g_pcm[NB*4*LD], g_pcs[NB*4*LD];
__device__ float g_part[2*NB*4*LD];

// ------------------------- helpers ------------------------------------------
__device__ __forceinline__ float tanh_ap(float x){
    float r; asm("tanh.approx.f32 %0, %1;" : "=f"(r) : "f"(x)); return r;
}
__device__ __forceinline__ void mma16(float* c, unsigned a0,unsigned a1,unsigned a2,unsigned a3,
                                      unsigned b0,unsigned b1){
    asm volatile("mma.sync.aligned.m16n8k16.row.col.f32.f16.f16.f32 "
        "{%0,%1,%2,%3}, {%4,%5,%6,%7}, {%8,%9}, {%0,%1,%2,%3};"
        : "+f"(c[0]),"+f"(c[1]),"+f"(c[2]),"+f"(c[3])
        : "r"(a0),"r"(a1),"r"(a2),"r"(a3),"r"(b0),"r"(b1));
}
__device__ __forceinline__ void ldmx4(unsigned* r, unsigned addr){
    asm volatile("ldmatrix.sync.aligned.m8n8.x4.shared.b16 {%0,%1,%2,%3}, [%4];"
        : "=r"(r[0]),"=r"(r[1]),"=r"(r[2]),"=r"(r[3]) : "r"(addr));
}
__device__ __forceinline__ void cpasync16(unsigned saddr, const void* g){
    asm volatile("cp.async.cg.shared.global [%0], [%1], 16;" :: "r"(saddr), "l"(g));
}
__device__ __forceinline__ void cpcommit(){ asm volatile("cp.async.commit_group;"); }
template<int N> __device__ __forceinline__ void cpwait(){
    asm volatile("cp.async.wait_group %0;" :: "n"(N));
}
__device__ __forceinline__ unsigned hmul2u(unsigned a, unsigned b){
    __half2 r = __hmul2(*(__half2*)&a, *(__half2*)&b);
    return *(unsigned*)&r;
}
// stage one 128x64 fp16 tile (16 KB) with 256 threads; XOR swizzle g^(r&7)
__device__ __forceinline__ void stage_cph(unsigned sbase, const __half* g, int tid){
    #pragma unroll
    for (int q = 0; q < 4; q++){
        int idx = tid + (q << 8);
        int r = idx >> 3, gs = idx & 7;
        cpasync16(sbase + (unsigned)(((r << 5) + ((gs ^ (r & 7)) << 2)) << 2),
                  g + (size_t)r * LD + (gs << 3));
    }
}
// fragment base offsets (bytes); per-ks address = (base+off) ^ (ks<<5)
__device__ __forceinline__ unsigned a_off(int row0, int lane){
    int sub = lane >> 3;
    int r = row0 + (lane & 7) + ((sub & 1) << 3);
    int g = (sub >> 1) ^ (r & 7);
    return (unsigned)(((r << 5) + (g << 2)) << 2);
}
__device__ __forceinline__ unsigned b_off(int n0, int lane){
    int sub = lane >> 3;
    int n = n0 + (lane & 7) + ((sub >> 1) << 3);
    int g = (sub & 1) ^ (n & 7);
    return (unsigned)(((n << 5) + (g << 2)) << 2);
}

// ---------------------------------------------------------------------------
// k_conv: fp32 -> fp16 copies (row-major for I/J) + fp16 transposes (I,J,W).
// ---------------------------------------------------------------------------
__global__ __launch_bounds__(256) void k_conv(const float* __restrict__ Jg,
                                              const float* __restrict__ Ig,
                                              const float* __restrict__ Wg)
{
    __shared__ float s[64][65];
    const int z = blockIdx.z;
    const int which = (z >= 64) ? 2 : (z >= 32 ? 1 : 0);
    const int b = (which == 0) ? z : (which == 1 ? z - 32 : 0);
    const float* sp = (which == 0 ? Jg : which == 1 ? Ig : Wg) + (size_t)b*LD*LD;
    __half* dn = (which == 0 ? g_jh : which == 1 ? g_ih : (__half*)0);
    __half* dt = (which == 0 ? g_jT : which == 1 ? g_iT : g_wT);
    if (dn) dn += (size_t)b*LD*LD;
    dt += (size_t)b*LD*LD;
    const int r0 = blockIdx.y*64, c0 = blockIdx.x*64;
    const int tid = threadIdx.x;
    const int tr = tid >> 4, tc = (tid & 15) << 2;
    #pragma unroll
    for (int rr = 0; rr < 4; rr++){
        int r = tr + (rr << 4);
        float4 v = *(const float4*)&sp[(size_t)(r0 + r)*LD + c0 + tc];
        if (dn){
            __half2* p = (__half2*)&dn[(size_t)(r0 + r)*LD + c0 + tc];
            p[0] = __floats2half2_rn(v.x, v.y);
            p[1] = __floats2half2_rn(v.z, v.w);
        }
        s[tc+0][r] = v.x; s[tc+1][r] = v.y; s[tc+2][r] = v.z; s[tc+3][r] = v.w;
    }
    __syncthreads();
    #pragma unroll
    for (int rr = 0; rr < 4; rr++){
        int r = tr + (rr << 4);
        __half2* p = (__half2*)&dt[(size_t)(c0 + r)*LD + r0 + tc];
        p[0] = __floats2half2_rn(s[r][tc],   s[r][tc+1]);
        p[1] = __floats2half2_rn(s[r][tc+2], s[r][tc+3]);
    }
}

// ---------------------------------------------------------------------------
// k_scores: S = I @ J^T (fp16 mma). 256 thr, 8 warps 64x32.
// Pipeline: wait<1> -> sync -> prefetch(ch+2) -> commit -> compute(ch).
// ---------------------------------------------------------------------------
__global__ __launch_bounds__(256,2) void k_scores()
{
    extern __shared__ float smem_raw[];
    unsigned su0 = (unsigned)__cvta_generic_to_shared(smem_raw);
    unsigned su = (su0 + 127u) & ~127u;
    float* smem = smem_raw + ((su - su0) >> 2);
    const int b = blockIdx.z, m0 = blockIdx.y*128, n0 = blockIdx.x*128;
    const __half* A = g_ih + (size_t)b*LD*LD + (size_t)m0*LD;
    const __half* B = g_jh + (size_t)b*LD*LD + (size_t)n0*LD;
    __half* C  = g_S  + (size_t)b*LD*LD;
    __half* CT = g_ST + (size_t)b*LD*LD;
    const int tid = threadIdx.x, lane = tid & 31, warp = tid >> 5;
    const int wm0 = (warp & 1) << 6, wn0 = (warp >> 1) << 5;
    unsigned aoff[4], boff[2];
    #pragma unroll
    for (int mt = 0; mt < 4; mt++) aoff[mt] = a_off(wm0 + (mt<<4), lane);
    #pragma unroll
    for (int p = 0; p < 2; p++) boff[p] = TILE_B + b_off(wn0 + (p<<4), lane);
    float c[4][4][4] = {};

    stage_cph(su,          A,      tid); stage_cph(su + TILE_B,      B,      tid); cpcommit();
    stage_cph(su + S2,     A + 64, tid); stage_cph(su + S2 + TILE_B, B + 64, tid); cpcommit();
    int st = 0, pf = 2;
    #pragma unroll 1
    for (int ch = 0; ch < 8; ch++){
        cpwait<1>(); __syncthreads();
        if (ch < 6){
            unsigned pb = su + pf*S2;
            stage_cph(pb,          A + (ch+2)*64, tid);
            stage_cph(pb + TILE_B, B + (ch+2)*64, tid);
        }
        cpcommit();
        unsigned sb = su + st*S2;
        unsigned ab[4], bb[2];
        #pragma unroll
        for (int mt = 0; mt < 4; mt++) ab[mt] = sb + aoff[mt];
        #pragma unroll
        for (int p = 0; p < 2; p++) bb[p] = sb + boff[p];
        #pragma unroll
        for (int ks = 0; ks < 4; ks++){
            unsigned xr = (unsigned)(ks << 5);
            unsigned braw[2][4];
            ldmx4(braw[0], bb[0] ^ xr);
            ldmx4(braw[1], bb[1] ^ xr);
            #pragma unroll
            for (int mt = 0; mt < 4; mt++){
                unsigned af[4];
                ldmx4(af, ab[mt] ^ xr);
                #pragma unroll
                for (int nt = 0; nt < 4; nt++){
                    int p = nt >> 1, q = (nt & 1) << 1;
                    mma16(c[mt][nt], af[0],af[1],af[2],af[3], braw[p][q], braw[p][q+1]);
                }
            }
        }
        st = (st==2)?0:st+1; pf = (pf==2)?0:pf+1;
    }
    __syncthreads();   // all compute done before epilogue reuses smem

    // --- epilogue A: row-softmax partials + E_row store (fp16) ---
    {
        float* prm = smem;
        float* prs = smem + 512;
        float* Mrow = smem + 1024;
        const int wn_idx = warp >> 1;
        #pragma unroll
        for (int mt = 0; mt < 4; mt++){
            float mx1 = -1e30f, mx2 = -1e30f;
            #pragma unroll
            for (int nt = 0; nt < 4; nt++){
                mx1 = fmaxf(mx1, fmaxf(c[mt][nt][0], c[mt][nt][1]));
                mx2 = fmaxf(mx2, fmaxf(c[mt][nt][2], c[mt][nt][3]));
            }
            #pragma unroll
            for (int o = 1; o <= 2; o <<= 1){
                mx1 = fmaxf(mx1, __shfl_xor_sync(0xffffffffu, mx1, o));
                mx2 = fmaxf(mx2, __shfl_xor_sync(0xffffffffu, mx2, o));
            }
            float s1 = 0.f, s2 = 0.f;
            #pragma unroll
            for (int nt = 0; nt < 4; nt++){
                s1 += __expf(c[mt][nt][0]-mx1) + __expf(c[mt][nt][1]-mx1);
                s2 += __expf(c[mt][nt][2]-mx2) + __expf(c[mt][nt][3]-mx2);
            }
            #pragma unroll
            for (int o = 1; o <= 2; o <<= 1){
                s1 += __shfl_xor_sync(0xffffffffu, s1, o);
                s2 += __shfl_xor_sync(0xffffffffu, s2, o);
            }
            if ((lane & 3) == 0){
                int r1 = wm0 + (mt<<4) + (lane>>2);
                prm[wn_idx*128 + r1]     = mx1; prs[wn_idx*128 + r1]     = s1;
                prm[wn_idx*128 + r1 + 8] = mx2; prs[wn_idx*128 + r1 + 8] = s2;
            }
        }
        __syncthreads();
        if (tid < 128){
            float M = -1e30f;
            #pragma unroll
            for (int w = 0; w < 4; w++) M = fmaxf(M, prm[w*128 + tid]);
            float S = 0.f;
            #pragma unroll
            for (int w = 0; w < 4; w++) S += prs[w*128 + tid] * __expf(prm[w*128 + tid] - M);
            int gi = (b*4 + blockIdx.x)*LD + m0 + tid;
            g_prm[gi] = M; g_prs[gi] = S;
            Mrow[tid] = M;
        }
        __syncthreads();
        #pragma unroll
        for (int mt = 0; mt < 4; mt++){
            int r1 = wm0 + (mt<<4) + (lane>>2);
            float M1 = Mrow[r1], M2 = Mrow[r1 + 8];
            int row = m0 + r1;
            #pragma unroll
            for (int nt = 0; nt < 4; nt++){
                int col = n0 + wn0 + (nt<<3) + ((lane&3)<<1);
                *(__half2*)&C[(size_t)row*LD + col] =
                    __floats2half2_rn(__expf(c[mt][nt][0]-M1), __expf(c[mt][nt][1]-M1));
                *(__half2*)&C[(size_t)(row+8)*LD + col] =
                    __floats2half2_rn(__expf(c[mt][nt][2]-M2), __expf(c[mt][nt][3]-M2));
            }
        }
    }

    // --- epilogue B: E_col store (fp16) via smem transpose + col partials ---
    const int wh = wn0 >> 6;
    const int mtile4 = (b*4 + blockIdx.y)*LD;
    for (int h = 0; h < 2; h++){
        __syncthreads();
        if (wh == h){
            #pragma unroll
            for (int mt = 0; mt < 4; mt++){
                int rw = wm0 + (mt<<4) + (lane>>2);
                #pragma unroll
                for (int nt = 0; nt < 4; nt++){
                    int cl = wn0 - (h<<6) + (nt<<3) + ((lane&3)<<1);
                    smem[cl*132 + rw]       = c[mt][nt][0];
                    smem[(cl+1)*132 + rw]   = c[mt][nt][1];
                    smem[cl*132 + rw + 8]   = c[mt][nt][2];
                    smem[(cl+1)*132 + rw+8] = c[mt][nt][3];
                }
            }
        }
        __syncthreads();
        #pragma unroll
        for (int w2 = 0; w2 < 8; w2++){
            int orow = warp + (w2 << 3);
            float4 v = *(float4*)&smem[orow*132 + (lane<<2)];
            float mx = fmaxf(fmaxf(v.x, v.y), fmaxf(v.z, v.w));
            #pragma unroll
            for (int o = 16; o; o >>= 1) mx = fmaxf(mx, __shfl_xor_sync(0xffffffffu, mx, o));
            float4 e;
            e.x = __expf(v.x-mx); e.y = __expf(v.y-mx);
            e.z = __expf(v.z-mx); e.w = __expf(v.w-mx);
            __half2 h0 = __floats2half2_rn(e.x, e.y);
            __half2 h1 = __floats2half2_rn(e.z, e.w);
            __half2* dst = (__half2*)&CT[(size_t)(n0 + (h<<6) + orow)*LD + m0 + (lane<<2)];
            dst[0] = h0; dst[1] = h1;
            float s = e.x + e.y + e.z + e.w;
            #pragma unroll
            for (int o = 16; o; o >>= 1) s += __shfl_xor_sync(0xffffffffu, s, o);
            if (lane == 0){
                int gi = mtile4 + n0 + (h<<6) + orow;
                g_pcm[gi] = mx; g_pcs[gi] = s;
            }
        }
    }
}

// ---------------------------------------------------------------------------
// k_wjwi: 256 thr, warp tile 32x64. which=0: D_i = |i - P_row@J|; which=1 sym.
// Prologue folds k_finish: combine per-tile softmax partials into rescale
// factors in smem, then preload hscl registers.
// ---------------------------------------------------------------------------
__global__ __launch_bounds__(256,2) void k_wjwi()
{
    extern __shared__ float smem_raw[];
    unsigned su0 = (unsigned)__cvta_generic_to_shared(smem_raw);
    unsigned su = (su0 + 127u) & ~127u;
    float* smem = smem_raw + ((su - su0) >> 2);
    float* ssc = smem + 3*S2/4;                 // [4][128] rescale factors
    const int z = blockIdx.z, b = z >> 1, which = z & 1;
    const int m0 = blockIdx.y*128, n0 = blockIdx.x*128;
    const __half* A  = (which ? g_ST : g_S ) + (size_t)b*LD*LD + (size_t)m0*LD;
    const __half* B  = (which ? g_iT : g_jT) + (size_t)b*LD*LD + (size_t)n0*LD;
    __half*       C  = (which ? g_Dj : g_Di) + (size_t)b*LD*LD;
    const __half* X  = (which ? g_jh : g_ih) + (size_t)b*LD*LD;
    const float* PM = (which ? g_pcm : g_prm) + b*4*LD + m0;
    const float* PS = (which ? g_pcs : g_prs) + b*4*LD + m0;
    const int tid = threadIdx.x, lane = tid & 31, warp = tid >> 5;
    const int wm0 = (warp & 3) << 5, wn0 = (warp >> 2) << 6;
    unsigned aoff[2], boff[4];
    #pragma unroll
    for (int mt = 0; mt < 2; mt++) aoff[mt] = a_off(wm0 + (mt<<4), lane);
    #pragma unroll
    for (int p = 0; p < 4; p++) boff[p] = TILE_B + b_off(wn0 + (p<<4), lane);

    // --- fold of k_finish: per-row combine of 4 tile partials ---
    if (tid < 128){
        float pm[4];
        #pragma unroll
        for (int t = 0; t < 4; t++) pm[t] = PM[t*LD + tid];
        float M = fmaxf(fmaxf(pm[0], pm[1]), fmaxf(pm[2], pm[3]));
        float S = 0.f;
        #pragma unroll
        for (int t = 0; t < 4; t++) S += PS[t*LD + tid] * __expf(pm[t] - M);
        float inv = 1.0f / S;
        #pragma unroll
        for (int t = 0; t < 4; t++) ssc[t*128 + tid] = __expf(pm[t] - M) * inv;
    }
    __syncthreads();
    unsigned hscl[4][2][2];
    #pragma unroll
    for (int t = 0; t < 4; t++)
        #pragma unroll
        for (int mt = 0; mt < 2; mt++)
            #pragma unroll
            for (int u = 0; u < 2; u++){
                __half2 h = __float2half2_rn(ssc[t*128 + wm0 + (mt<<4) + (lane>>2) + (u<<3)]);
                hscl[t][mt][u] = *(unsigned*)&h;
            }
    float c[2][8][4] = {};

    stage_cph(su,          A,      tid); stage_cph(su + TILE_B,      B,      tid); cpcommit();
    stage_cph(su + S2,     A + 64, tid); stage_cph(su + S2 + TILE_B, B + 64, tid); cpcommit();
    int st = 0, pf = 2;
    #pragma unroll 1
    for (int ch = 0; ch < 8; ch++){
        const int t = ch >> 1;
        cpwait<1>(); __syncthreads();
        if (ch < 6){
            unsigned pb = su + pf*S2;
            stage_cph(pb,          A + (ch+2)*64, tid);
            stage_cph(pb + TILE_B, B + (ch+2)*64, tid);
        }
        cpcommit();
        unsigned sb = su + st*S2;
        unsigned ab[2], bb[4];
        #pragma unroll
        for (int mt = 0; mt < 2; mt++) ab[mt] = sb + aoff[mt];
        #pragma unroll
        for (int p = 0; p < 4; p++) bb[p] = sb + boff[p];
        #pragma unroll
        for (int ks = 0; ks < 4; ks++){
            unsigned xr = (unsigned)(ks << 5);
            unsigned braw[4][4];
            #pragma unroll
            for (int p = 0; p < 4; p++) ldmx4(braw[p], bb[p] ^ xr);
            #pragma unroll
            for (int mt = 0; mt < 2; mt++){
                unsigned ar[4], af[4];
                ldmx4(ar, ab[mt] ^ xr);
                #pragma unroll
                for (int zz = 0; zz < 4; zz++)
                    af[zz] = hmul2u(ar[zz], hscl[t][mt][zz&1]);
                #pragma unroll
                for (int nt = 0; nt < 8; nt++){
                    int p = nt >> 1, q = (nt & 1) << 1;
                    mma16(c[mt][nt], af[0],af[1],af[2],af[3], braw[p][q], braw[p][q+1]);
                }
            }
        }
        st = (st==2)?0:st+1; pf = (pf==2)?0:pf+1;
    }
    // epilogue: D = fp16(|x - acc|)
    #pragma unroll
    for (int mt = 0; mt < 2; mt++){
        int row = m0 + wm0 + (mt<<4) + (lane>>2);
        #pragma unroll
        for (int nt = 0; nt < 8; nt++){
            int col = n0 + wn0 + (nt<<3) + ((lane&3)<<1);
            float2 x1 = __half22float2(*(const __half2*)&X[(size_t)row*LD + col]);
            float2 x2 = __half22float2(*(const __half2*)&X[(size_t)(row+8)*LD + col]);
            *(__half2*)&C[(size_t)row*LD + col] =
                __floats2half2_rn(fabsf(x1.x - c[mt][nt][0]), fabsf(x1.y - c[mt][nt][1]));
            *(__half2*)&C[(size_t)(row+8)*LD + col] =
                __floats2half2_rn(fabsf(x2.x - c[mt][nt][2]), fabsf(x2.y - c[mt][nt][3]));
        }
    }
}

// ---------------------------------------------------------------------------
// k_agg: 256 thr, warp tile 64x32; partial colsum of tanh(D @ wT + bias).
// ---------------------------------------------------------------------------
__global__ __launch_bounds__(256,2) void k_agg(const float* __restrict__ bias)
{
    extern __shared__ float smem_raw[];
    unsigned su0 = (unsigned)__cvta_generic_to_shared(smem_raw);
    unsigned su = (su0 + 127u) & ~127u;
    float* smem = smem_raw + ((su - su0) >> 2);
    const int bx = blockIdx.x, b = blockIdx.y, which = blockIdx.z;
    const int n0 = (bx & 3) << 7, mb = bx >> 2;
    const __half* D  = (which ? g_Dj : g_Di) + (size_t)b*LD*LD + (size_t)(mb<<7)*LD;
    const __half* Bm = g_wT + (size_t)n0*LD;
    float* Og = g_part + (size_t)((((which*NB) + b)<<2) + mb)*LD;
    const int tid = threadIdx.x, lane = tid & 31, warp = tid >> 5;
    const int wm0 = (warp & 1) << 6, wn0 = (warp >> 1) << 5;
    unsigned aoff[4], boff[2];
    #pragma unroll
    for (int mt = 0; mt < 4; mt++) aoff[mt] = a_off(wm0 + (mt<<4), lane);
    #pragma unroll
    for (int p = 0; p < 2; p++) boff[p] = TILE_B + b_off(wn0 + (p<<4), lane);
    float bia[4][2];
    #pragma unroll
    for (int nt = 0; nt < 4; nt++){
        int col = n0 + wn0 + (nt<<3) + ((lane&3)<<1);
        bia[nt][0] = bias[col]; bia[nt][1] = bias[col+1];
    }
    float c[4][4][4] = {};

    stage_cph(su,          D,      tid); stage_cph(su + TILE_B,      Bm,      tid); cpcommit();
    stage_cph(su + S2,     D + 64, tid); stage_cph(su + S2 + TILE_B, Bm + 64, tid); cpcommit();
    int st = 0, pf = 2;
    #pragma unroll 1
    for (int ch = 0; ch < 8; ch++){
        cpwait<1>(); __syncthreads();
        if (ch < 6){
            unsigned pb = su + pf*S2;
            stage_cph(pb,          D  + (ch+2)*64, tid);
            stage_cph(pb + TILE_B, Bm + (ch+2)*64, tid);
        }
        cpcommit();
        unsigned sb = su + st*S2;
        unsigned ab[4], bb[2];
        #pragma unroll
        for (int mt = 0; mt < 4; mt++) ab[mt] = sb + aoff[mt];
        #pragma unroll
        for (int p = 0; p < 2; p++) bb[p] = sb + boff[p];
        #pragma unroll
        for (int ks = 0; ks < 4; ks++){
            unsigned xr = (unsigned)(ks << 5);
            unsigned braw[2][4];
            ldmx4(braw[0], bb[0] ^ xr);
            ldmx4(braw[1], bb[1] ^ xr);
            #pragma unroll
            for (int mt = 0; mt < 4; mt++){
                unsigned af[4];
                ldmx4(af, ab[mt] ^ xr);
                #pragma unroll
                for (int nt = 0; nt < 4; nt++){
                    int p = nt >> 1, q = (nt & 1) << 1;
                    mma16(c[mt][nt], af[0],af[1],af[2],af[3], braw[p][q], braw[p][q+1]);
                }
            }
        }
        st = (st==2)?0:st+1; pf = (pf==2)?0:pf+1;
    }
    __syncthreads();   // compute done before smem reuse for reduction
    float csum[4][2] = {};
    #pragma unroll
    for (int mt = 0; mt < 4; mt++)
        #pragma unroll
        for (int nt = 0; nt < 4; nt++){
            csum[nt][0] += tanh_ap(c[mt][nt][0] + bia[nt][0]) + tanh_ap(c[mt][nt][2] + bia[nt][0]);
            csum[nt][1] += tanh_ap(c[mt][nt][1] + bia[nt][1]) + tanh_ap(c[mt][nt][3] + bia[nt][1]);
        }
    #pragma unroll
    for (int nt = 0; nt < 4; nt++)
        #pragma unroll
        for (int u = 0; u < 2; u++){
            float s = csum[nt][u];
            s += __shfl_xor_sync(0xffffffffu, s, 4);
            s += __shfl_xor_sync(0xffffffffu, s, 8);
            s += __shfl_xor_sync(0xffffffffu, s, 16);
            csum[nt][u] = s;
        }
    float* red = smem;
    if ((lane >> 2) == 0){
        #pragma unroll
        for (int nt = 0; nt < 4; nt++){
            int col = wn0 + (nt<<3) + ((lane&3)<<1);
            red[(warp&1)*128 + col]     = csum[nt][0];
            red[(warp&1)*128 + col + 1] = csum[nt][1];
        }
    }
    __syncthreads();
    if (tid < 128) Og[n0 + tid] = red[tid] + red[128 + tid];
}

// ---------------------------------------------------------------------------
__global__ void k_combine(float* __restrict__ out)
{
    const int idx = blockIdx.x * 256 + threadIdx.x;
    const int b = idx >> 9, h = idx & 511;
    float s = 0.f;
    #pragma unroll
    for (int w = 0; w < 2; w++)
        #pragma unroll
        for (int mb = 0; mb < 4; mb++)
            s += g_part[(size_t)((((w*NB) + b)<<2) + mb)*LD + h];
    out[idx] = s * (0.5f / 512.0f);
}

// ---------------------------------------------------------------------------
extern "C" void kernel_launch(void* const* d_in, const int* in_sizes, int n_in,
                              void* d_out, int out_size)
{
    (void)in_sizes; (void)n_in; (void)out_size;
    const float* I    = (const float*)d_in[0];
    const float* J    = (const float*)d_in[1];
    const float* W    = (const float*)d_in[2];
    const float* bias = (const float*)d_in[3];
    float* out = (float*)d_out;

    const int SM  = 3*S2 + 256;
    const int SMW = 3*S2 + 4*128*4 + 256;   // + ssc[4][128]
    cudaFuncSetAttribute(k_scores, cudaFuncAttributeMaxDynamicSharedMemorySize, SM);
    cudaFuncSetAttribute(k_wjwi,   cudaFuncAttributeMaxDynamicSharedMemorySize, SMW);
    cudaFuncSetAttribute(k_agg,    cudaFuncAttributeMaxDynamicSharedMemorySize, SM);

    k_conv   <<<dim3(8,8,65), 256>>>(J, I, W);
    k_scores <<<dim3(4,4,NB),   256, SM>>>();
    k_wjwi   <<<dim3(4,4,2*NB), 256, SMW>>>();
    k_agg    <<<dim3(16,NB,2),  256, SM>>>(bias);
    k_combine<<<64, 256>>>(out);
}

// round 16
// speedup vs baseline: 1.5274x; 1.5274x over previous
#include <cuda_runtime.h>
#include <cuda_fp16.h>
#include <math.h>

#define LD 512
#define NB 32
#define NBLD (NB*LD)
#define TILE_B 16384          // bytes per 128x64 fp16 tile (BK=64)
#define S2 (2*TILE_B)         // bytes per pipeline stage (2 tiles)

// ---------------- scratch (declared as float for 16B-safe alignment) --------
__device__ float g_S_raw [(size_t)NB*LD*LD/2];  // E_row fp16
__device__ float g_ST_raw[(size_t)NB*LD*LD/2];  // E_col fp16
__device__ float g_Di_raw[(size_t)NB*LD*LD/2];  // D_i = |i - wj| fp16
__device__ float g_Dj_raw[(size_t)NB*LD*LD/2];  // D_j = |j - wi| fp16
__device__ float g_ih_raw[(size_t)NB*LD*LD/2];  // I fp16 row-major
__device__ float g_jh_raw[(size_t)NB*LD*LD/2];  // J fp16 row-major
__device__ float g_iT_raw[(size_t)NB*LD*LD/2];  // I^T fp16
__device__ float g_jT_raw[(size_t)NB*LD*LD/2];  // J^T fp16
__device__ float g_wT_raw[(size_t)LD*LD/2];     // W^T fp16
#define g_S  ((__half*)g_S_raw)
#define g_ST ((__half*)g_ST_raw)
#define g_Di ((__half*)g_Di_raw)
#define g_Dj ((__half*)g_Dj_raw)
#define g_ih ((__half*)g_ih_raw)
#define g_jh ((__half*)g_jh_raw)
#define g_iT ((__half*)g_iT_raw)
#define g_jT ((__half*)g_jT_raw)
#define g_wT ((__half*)g_wT_raw)
__device__ float g_prm[NB*4*LD], g_prs[NB*4*LD];
__device__ float g_pcm[NB*4*LD], g_pcs[NB*4*LD];
__device__ float g_rscl[NB*4*LD], g_cscl[NB*4*LD];
__device__ float g_part[2*NB*4*LD];

// ------------------------- helpers ------------------------------------------
__device__ __forceinline__ float tanh_ap(float x){
    float r; asm("tanh.approx.f32 %0, %1;" : "=f"(r) : "f"(x)); return r;
}
__device__ __forceinline__ void mma16(float* c, unsigned a0,unsigned a1,unsigned a2,unsigned a3,
                                      unsigned b0,unsigned b1){
    asm volatile("mma.sync.aligned.m16n8k16.row.col.f32.f16.f16.f32 "
        "{%0,%1,%2,%3}, {%4,%5,%6,%7}, {%8,%9}, {%0,%1,%2,%3};"
        : "+f"(c[0]),"+f"(c[1]),"+f"(c[2]),"+f"(c[3])
        : "r"(a0),"r"(a1),"r"(a2),"r"(a3),"r"(b0),"r"(b1));
}
__device__ __forceinline__ void ldmx4(unsigned* r, unsigned addr){
    asm volatile("ldmatrix.sync.aligned.m8n8.x4.shared.b16 {%0,%1,%2,%3}, [%4];"
        : "=r"(r[0]),"=r"(r[1]),"=r"(r[2]),"=r"(r[3]) : "r"(addr));
}
__device__ __forceinline__ void cpasync16(unsigned saddr, const void* g){
    asm volatile("cp.async.cg.shared.global [%0], [%1], 16;" :: "r"(saddr), "l"(g));
}
__device__ __forceinline__ void cpcommit(){ asm volatile("cp.async.commit_group;"); }
template<int N> __device__ __forceinline__ void cpwait(){
    asm volatile("cp.async.wait_group %0;" :: "n"(N));
}
__device__ __forceinline__ unsigned hmul2u(unsigned a, unsigned b){
    __half2 r = __hmul2(*(__half2*)&a, *(__half2*)&b);
    return *(unsigned*)&r;
}
// stage one 128x64 fp16 tile (16 KB) with 256 threads; XOR swizzle g^(r&7)
__device__ __forceinline__ void stage_cph(unsigned sbase, const __half* g, int tid){
    #pragma unroll
    for (int q = 0; q < 4; q++){
        int idx = tid + (q << 8);
        int r = idx >> 3, gs = idx & 7;
        cpasync16(sbase + (unsigned)(((r << 5) + ((gs ^ (r & 7)) << 2)) << 2),
                  g + (size_t)r * LD + (gs << 3));
    }
}
// fragment base offsets (bytes); per-ks address = (base+off) ^ (ks<<5)
__device__ __forceinline__ unsigned a_off(int row0, int lane){
    int sub = lane >> 3;
    int r = row0 + (lane & 7) + ((sub & 1) << 3);
    int g = (sub >> 1) ^ (r & 7);
    return (unsigned)(((r << 5) + (g << 2)) << 2);
}
__device__ __forceinline__ unsigned b_off(int n0, int lane){
    int sub = lane >> 3;
    int n = n0 + (lane & 7) + ((sub >> 1) << 3);
    int g = (sub & 1) ^ (n & 7);
    return (unsigned)(((n << 5) + (g << 2)) << 2);
}

// ---------------------------------------------------------------------------
// k_conv: fp32 -> fp16 copies (row-major for I/J) + fp16 transposes (I,J,W).
// ---------------------------------------------------------------------------
__global__ __launch_bounds__(256) void k_conv(const float* __restrict__ Jg,
                                              const float* __restrict__ Ig,
                                              const float* __restrict__ Wg)
{
    __shared__ float s[64][65];
    const int z = blockIdx.z;
    const int which = (z >= 64) ? 2 : (z >= 32 ? 1 : 0);
    const int b = (which == 0) ? z : (which == 1 ? z - 32 : 0);
    const float* sp = (which == 0 ? Jg : which == 1 ? Ig : Wg) + (size_t)b*LD*LD;
    __half* dn = (which == 0 ? g_jh : which == 1 ? g_ih : (__half*)0);
    __half* dt = (which == 0 ? g_jT : which == 1 ? g_iT : g_wT);
    if (dn) dn += (size_t)b*LD*LD;
    dt += (size_t)b*LD*LD;
    const int r0 = blockIdx.y*64, c0 = blockIdx.x*64;
    const int tid = threadIdx.x;
    const int tr = tid >> 4, tc = (tid & 15) << 2;
    #pragma unroll
    for (int rr = 0; rr < 4; rr++){
        int r = tr + (rr << 4);
        float4 v = *(const float4*)&sp[(size_t)(r0 + r)*LD + c0 + tc];
        if (dn){
            __half2* p = (__half2*)&dn[(size_t)(r0 + r)*LD + c0 + tc];
            p[0] = __floats2half2_rn(v.x, v.y);
            p[1] = __floats2half2_rn(v.z, v.w);
        }
        s[tc+0][r] = v.x; s[tc+1][r] = v.y; s[tc+2][r] = v.z; s[tc+3][r] = v.w;
    }
    __syncthreads();
    #pragma unroll
    for (int rr = 0; rr < 4; rr++){
        int r = tr + (rr << 4);
        __half2* p = (__half2*)&dt[(size_t)(c0 + r)*LD + r0 + tc];
        p[0] = __floats2half2_rn(s[r][tc],   s[r][tc+1]);
        p[1] = __floats2half2_rn(s[r][tc+2], s[r][tc+3]);
    }
}

// ---------------------------------------------------------------------------
// k_scores: S = I @ J^T (fp16 mma). 256 thr, 8 warps 64x32.
// Pipeline: wait<1> -> sync -> prefetch(ch+2) -> commit -> compute(ch).
// ---------------------------------------------------------------------------
__global__ __launch_bounds__(256,2) void k_scores()
{
    extern __shared__ float smem_raw[];
    unsigned su0 = (unsigned)__cvta_generic_to_shared(smem_raw);
    unsigned su = (su0 + 127u) & ~127u;
    float* smem = smem_raw + ((su - su0) >> 2);
    const int b = blockIdx.z, m0 = blockIdx.y*128, n0 = blockIdx.x*128;
    const __half* A = g_ih + (size_t)b*LD*LD + (size_t)m0*LD;
    const __half* B = g_jh + (size_t)b*LD*LD + (size_t)n0*LD;
    __half* C  = g_S  + (size_t)b*LD*LD;
    __half* CT = g_ST + (size_t)b*LD*LD;
    const int tid = threadIdx.x, lane = tid & 31, warp = tid >> 5;
    const int wm0 = (warp & 1) << 6, wn0 = (warp >> 1) << 5;
    unsigned aoff[4], boff[2];
    #pragma unroll
    for (int mt = 0; mt < 4; mt++) aoff[mt] = a_off(wm0 + (mt<<4), lane);
    #pragma unroll
    for (int p = 0; p < 2; p++) boff[p] = TILE_B + b_off(wn0 + (p<<4), lane);
    float c[4][4][4] = {};

    stage_cph(su,          A,      tid); stage_cph(su + TILE_B,      B,      tid); cpcommit();
    stage_cph(su + S2,     A + 64, tid); stage_cph(su + S2 + TILE_B, B + 64, tid); cpcommit();
    int st = 0, pf = 2;
    #pragma unroll 1
    for (int ch = 0; ch < 8; ch++){
        cpwait<1>(); __syncthreads();
        if (ch < 6){
            unsigned pb = su + pf*S2;
            stage_cph(pb,          A + (ch+2)*64, tid);
            stage_cph(pb + TILE_B, B + (ch+2)*64, tid);
        }
        cpcommit();
        unsigned sb = su + st*S2;
        unsigned ab[4], bb[2];
        #pragma unroll
        for (int mt = 0; mt < 4; mt++) ab[mt] = sb + aoff[mt];
        #pragma unroll
        for (int p = 0; p < 2; p++) bb[p] = sb + boff[p];
        #pragma unroll
        for (int ks = 0; ks < 4; ks++){
            unsigned xr = (unsigned)(ks << 5);
            unsigned braw[2][4];
            ldmx4(braw[0], bb[0] ^ xr);
            ldmx4(braw[1], bb[1] ^ xr);
            #pragma unroll
            for (int mt = 0; mt < 4; mt++){
                unsigned af[4];
                ldmx4(af, ab[mt] ^ xr);
                #pragma unroll
                for (int nt = 0; nt < 4; nt++){
                    int p = nt >> 1, q = (nt & 1) << 1;
                    mma16(c[mt][nt], af[0],af[1],af[2],af[3], braw[p][q], braw[p][q+1]);
                }
            }
        }
        st = (st==2)?0:st+1; pf = (pf==2)?0:pf+1;
    }
    __syncthreads();   // all compute done before epilogue reuses smem

    // --- epilogue A: row-softmax partials + E_row store (fp16) ---
    {
        float* prm = smem;
        float* prs = smem + 512;
        float* Mrow = smem + 1024;
        const int wn_idx = warp >> 1;
        #pragma unroll
        for (int mt = 0; mt < 4; mt++){
            float mx1 = -1e30f, mx2 = -1e30f;
            #pragma unroll
            for (int nt = 0; nt < 4; nt++){
                mx1 = fmaxf(mx1, fmaxf(c[mt][nt][0], c[mt][nt][1]));
                mx2 = fmaxf(mx2, fmaxf(c[mt][nt][2], c[mt][nt][3]));
            }
            #pragma unroll
            for (int o = 1; o <= 2; o <<= 1){
                mx1 = fmaxf(mx1, __shfl_xor_sync(0xffffffffu, mx1, o));
                mx2 = fmaxf(mx2, __shfl_xor_sync(0xffffffffu, mx2, o));
            }
            float s1 = 0.f, s2 = 0.f;
            #pragma unroll
            for (int nt = 0; nt < 4; nt++){
                s1 += __expf(c[mt][nt][0]-mx1) + __expf(c[mt][nt][1]-mx1);
                s2 += __expf(c[mt][nt][2]-mx2) + __expf(c[mt][nt][3]-mx2);
            }
            #pragma unroll
            for (int o = 1; o <= 2; o <<= 1){
                s1 += __shfl_xor_sync(0xffffffffu, s1, o);
                s2 += __shfl_xor_sync(0xffffffffu, s2, o);
            }
            if ((lane & 3) == 0){
                int r1 = wm0 + (mt<<4) + (lane>>2);
                prm[wn_idx*128 + r1]     = mx1; prs[wn_idx*128 + r1]     = s1;
                prm[wn_idx*128 + r1 + 8] = mx2; prs[wn_idx*128 + r1 + 8] = s2;
            }
        }
        __syncthreads();
        if (tid < 128){
            float M = -1e30f;
            #pragma unroll
            for (int w = 0; w < 4; w++) M = fmaxf(M, prm[w*128 + tid]);
            float S = 0.f;
            #pragma unroll
            for (int w = 0; w < 4; w++) S += prs[w*128 + tid] * __expf(prm[w*128 + tid] - M);
            int gi = (b*4 + blockIdx.x)*LD + m0 + tid;
            g_prm[gi] = M; g_prs[gi] = S;
            Mrow[tid] = M;
        }
        __syncthreads();
        #pragma unroll
        for (int mt = 0; mt < 4; mt++){
            int r1 = wm0 + (mt<<4) + (lane>>2);
            float M1 = Mrow[r1], M2 = Mrow[r1 + 8];
            int row = m0 + r1;
            #pragma unroll
            for (int nt = 0; nt < 4; nt++){
                int col = n0 + wn0 + (nt<<3) + ((lane&3)<<1);
                *(__half2*)&C[(size_t)row*LD + col] =
                    __floats2half2_rn(__expf(c[mt][nt][0]-M1), __expf(c[mt][nt][1]-M1));
                *(__half2*)&C[(size_t)(row+8)*LD + col] =
                    __floats2half2_rn(__expf(c[mt][nt][2]-M2), __expf(c[mt][nt][3]-M2));
            }
        }
    }

    // --- epilogue B: E_col store (fp16) via smem transpose + col partials ---
    const int wh = wn0 >> 6;
    const int mtile4 = (b*4 + blockIdx.y)*LD;
    for (int h = 0; h < 2; h++){
        __syncthreads();
        if (wh == h){
            #pragma unroll
            for (int mt = 0; mt < 4; mt++){
                int rw = wm0 + (mt<<4) + (lane>>2);
                #pragma unroll
                for (int nt = 0; nt < 4; nt++){
                    int cl = wn0 - (h<<6) + (nt<<3) + ((lane&3)<<1);
                    smem[cl*132 + rw]       = c[mt][nt][0];
                    smem[(cl+1)*132 + rw]   = c[mt][nt][1];
                    smem[cl*132 + rw + 8]   = c[mt][nt][2];
                    smem[(cl+1)*132 + rw+8] = c[mt][nt][3];
                }
            }
        }
        __syncthreads();
        #pragma unroll
        for (int w2 = 0; w2 < 8; w2++){
            int orow = warp + (w2 << 3);
            float4 v = *(float4*)&smem[orow*132 + (lane<<2)];
            float mx = fmaxf(fmaxf(v.x, v.y), fmaxf(v.z, v.w));
            #pragma unroll
            for (int o = 16; o; o >>= 1) mx = fmaxf(mx, __shfl_xor_sync(0xffffffffu, mx, o));
            float4 e;
            e.x = __expf(v.x-mx); e.y = __expf(v.y-mx);
            e.z = __expf(v.z-mx); e.w = __expf(v.w-mx);
            __half2 h0 = __floats2half2_rn(e.x, e.y);
            __half2 h1 = __floats2half2_rn(e.z, e.w);
            __half2* dst = (__half2*)&CT[(size_t)(n0 + (h<<6) + orow)*LD + m0 + (lane<<2)];
            dst[0] = h0; dst[1] = h1;
            float s = e.x + e.y + e.z + e.w;
            #pragma unroll
            for (int o = 16; o; o >>= 1) s += __shfl_xor_sync(0xffffffffu, s, o);
            if (lane == 0){
                int gi = mtile4 + n0 + (h<<6) + orow;
                g_pcm[gi] = mx; g_pcs[gi] = s;
            }
        }
    }
}

// ---------------------------------------------------------------------------
// k_finish: per-row global stats -> per-k-tile rescale factors exp(pm-M)/Z.
// ---------------------------------------------------------------------------
__global__ __launch_bounds__(256) void k_finish()
{
    const int idx = blockIdx.x * 256 + threadIdx.x;
    const bool cs = idx >= NBLD;
    const int r = cs ? idx - NBLD : idx;
    const int base = ((r >> 9) << 2)*LD + (r & 511);
    const float* PM = (cs ? g_pcm : g_prm) + base;
    const float* PS = (cs ? g_pcs : g_prs) + base;
    float pm[4];
    #pragma unroll
    for (int t = 0; t < 4; t++) pm[t] = PM[t*LD];
    float M = fmaxf(fmaxf(pm[0], pm[1]), fmaxf(pm[2], pm[3]));
    float S = 0.f;
    #pragma unroll
    for (int t = 0; t < 4; t++) S += PS[t*LD] * __expf(pm[t] - M);
    float inv = 1.0f / S;
    float* OUT = (cs ? g_cscl : g_rscl) + base;
    #pragma unroll
    for (int t = 0; t < 4; t++) OUT[t*LD] = __expf(pm[t] - M) * inv;
}

// ---------------------------------------------------------------------------
// k_wjwi: 256 thr, warp tile 32x64. which=0: D_i = |i - P_row@J|; which=1 sym.
// ---------------------------------------------------------------------------
__global__ __launch_bounds__(256,2) void k_wjwi()
{
    extern __shared__ float smem_raw[];
    unsigned su0 = (unsigned)__cvta_generic_to_shared(smem_raw);
    unsigned su = (su0 + 127u) & ~127u;
    const int z = blockIdx.z, b = z >> 1, which = z & 1;
    const int m0 = blockIdx.y*128, n0 = blockIdx.x*128;
    const __half* A  = (which ? g_ST : g_S ) + (size_t)b*LD*LD + (size_t)m0*LD;
    const __half* B  = (which ? g_iT : g_jT) + (size_t)b*LD*LD + (size_t)n0*LD;
    __half*       C  = (which ? g_Dj : g_Di) + (size_t)b*LD*LD;
    const __half* X  = (which ? g_jh : g_ih) + (size_t)b*LD*LD;
    const float* SC = (which ? g_cscl : g_rscl) + b*4*LD + m0;
    const int tid = threadIdx.x, lane = tid & 31, warp = tid >> 5;
    const int wm0 = (warp & 3) << 5, wn0 = (warp >> 2) << 6;
    unsigned aoff[2], boff[4];
    #pragma unroll
    for (int mt = 0; mt < 2; mt++) aoff[mt] = a_off(wm0 + (mt<<4), lane);
    #pragma unroll
    for (int p = 0; p < 4; p++) boff[p] = TILE_B + b_off(wn0 + (p<<4), lane);
    unsigned hscl[4][2][2];
    #pragma unroll
    for (int t = 0; t < 4; t++)
        #pragma unroll
        for (int mt = 0; mt < 2; mt++)
            #pragma unroll
            for (int u = 0; u < 2; u++){
                __half2 h = __float2half2_rn(SC[t*LD + wm0 + (mt<<4) + (lane>>2) + (u<<3)]);
                hscl[t][mt][u] = *(unsigned*)&h;
            }
    float c[2][8][4] = {};

    stage_cph(su,          A,      tid); stage_cph(su + TILE_B,      B,      tid); cpcommit();
    stage_cph(su + S2,     A + 64, tid); stage_cph(su + S2 + TILE_B, B + 64, tid); cpcommit();
    int st = 0, pf = 2;
    #pragma unroll 1
    for (int ch = 0; ch < 8; ch++){
        const int t = ch >> 1;
        cpwait<1>(); __syncthreads();
        if (ch < 6){
            unsigned pb = su + pf*S2;
            stage_cph(pb,          A + (ch+2)*64, tid);
            stage_cph(pb + TILE_B, B + (ch+2)*64, tid);
        }
        cpcommit();
        unsigned sb = su + st*S2;
        unsigned ab[2], bb[4];
        #pragma unroll
        for (int mt = 0; mt < 2; mt++) ab[mt] = sb + aoff[mt];
        #pragma unroll
        for (int p = 0; p < 4; p++) bb[p] = sb + boff[p];
        #pragma unroll
        for (int ks = 0; ks < 4; ks++){
            unsigned xr = (unsigned)(ks << 5);
            unsigned braw[4][4];
            #pragma unroll
            for (int p = 0; p < 4; p++) ldmx4(braw[p], bb[p] ^ xr);
            #pragma unroll
            for (int mt = 0; mt < 2; mt++){
                unsigned ar[4], af[4];
                ldmx4(ar, ab[mt] ^ xr);
                #pragma unroll
                for (int zz = 0; zz < 4; zz++)
                    af[zz] = hmul2u(ar[zz], hscl[t][mt][zz&1]);
                #pragma unroll
                for (int nt = 0; nt < 8; nt++){
                    int p = nt >> 1, q = (nt & 1) << 1;
                    mma16(c[mt][nt], af[0],af[1],af[2],af[3], braw[p][q], braw[p][q+1]);
                }
            }
        }
        st = (st==2)?0:st+1; pf = (pf==2)?0:pf+1;
    }
    // epilogue: D = fp16(|x - acc|)
    #pragma unroll
    for (int mt = 0; mt < 2; mt++){
        int row = m0 + wm0 + (mt<<4) + (lane>>2);
        #pragma unroll
        for (int nt = 0; nt < 8; nt++){
            int col = n0 + wn0 + (nt<<3) + ((lane&3)<<1);
            float2 x1 = __half22float2(*(const __half2*)&X[(size_t)row*LD + col]);
            float2 x2 = __half22float2(*(const __half2*)&X[(size_t)(row+8)*LD + col]);
            *(__half2*)&C[(size_t)row*LD + col] =
                __floats2half2_rn(fabsf(x1.x - c[mt][nt][0]), fabsf(x1.y - c[mt][nt][1]));
            *(__half2*)&C[(size_t)(row+8)*LD + col] =
                __floats2half2_rn(fabsf(x2.x - c[mt][nt][2]), fabsf(x2.y - c[mt][nt][3]));
        }
    }
}

// ---------------------------------------------------------------------------
// k_agg: 256 thr, warp tile 64x32; partial colsum of tanh(D @ wT + bias).
// ---------------------------------------------------------------------------
__global__ __launch_bounds__(256,2) void k_agg(const float* __restrict__ bias)
{
    extern __shared__ float smem_raw[];
    unsigned su0 = (unsigned)__cvta_generic_to_shared(smem_raw);
    unsigned su = (su0 + 127u) & ~127u;
    float* smem = smem_raw + ((su - su0) >> 2);
    const int bx = blockIdx.x, b = blockIdx.y, which = blockIdx.z;
    const int n0 = (bx & 3) << 7, mb = bx >> 2;
    const __half* D  = (which ? g_Dj : g_Di) + (size_t)b*LD*LD + (size_t)(mb<<7)*LD;
    const __half* Bm = g_wT + (size_t)n0*LD;
    float* Og = g_part + (size_t)((((which*NB) + b)<<2) + mb)*LD;
    const int tid = threadIdx.x, lane = tid & 31, warp = tid >> 5;
    const int wm0 = (warp & 1) << 6, wn0 = (warp >> 1) << 5;
    unsigned aoff[4], boff[2];
    #pragma unroll
    for (int mt = 0; mt < 4; mt++) aoff[mt] = a_off(wm0 + (mt<<4), lane);
    #pragma unroll
    for (int p = 0; p < 2; p++) boff[p] = TILE_B + b_off(wn0 + (p<<4), lane);
    float bia[4][2];
    #pragma unroll
    for (int nt = 0; nt < 4; nt++){
        int col = n0 + wn0 + (nt<<3) + ((lane&3)<<1);
        bia[nt][0] = bias[col]; bia[nt][1] = bias[col+1];
    }
    float c[4][4][4] = {};

    stage_cph(su,          D,      tid); stage_cph(su + TILE_B,      Bm,      tid); cpcommit();
    stage_cph(su + S2,     D + 64, tid); stage_cph(su + S2 + TILE_B, Bm + 64, tid); cpcommit();
    int st = 0, pf = 2;
    #pragma unroll 1
    for (int ch = 0; ch < 8; ch++){
        cpwait<1>(); __syncthreads();
        if (ch < 6){
            unsigned pb = su + pf*S2;
            stage_cph(pb,          D  + (ch+2)*64, tid);
            stage_cph(pb + TILE_B, Bm + (ch+2)*64, tid);
        }
        cpcommit();
        unsigned sb = su + st*S2;
        unsigned ab[4], bb[2];
        #pragma unroll
        for (int mt = 0; mt < 4; mt++) ab[mt] = sb + aoff[mt];
        #pragma unroll
        for (int p = 0; p < 2; p++) bb[p] = sb + boff[p];
        #pragma unroll
        for (int ks = 0; ks < 4; ks++){
            unsigned xr = (unsigned)(ks << 5);
            unsigned braw[2][4];
            ldmx4(braw[0], bb[0] ^ xr);
            ldmx4(braw[1], bb[1] ^ xr);
            #pragma unroll
            for (int mt = 0; mt < 4; mt++){
                unsigned af[4];
                ldmx4(af, ab[mt] ^ xr);
                #pragma unroll
                for (int nt = 0; nt < 4; nt++){
                    int p = nt >> 1, q = (nt & 1) << 1;
                    mma16(c[mt][nt], af[0],af[1],af[2],af[3], braw[p][q], braw[p][q+1]);
                }
            }
        }
        st = (st==2)?0:st+1; pf = (pf==2)?0:pf+1;
    }
    __syncthreads();   // compute done before smem reuse for reduction
    float csum[4][2] = {};
    #pragma unroll
    for (int mt = 0; mt < 4; mt++)
        #pragma unroll
        for (int nt = 0; nt < 4; nt++){
            csum[nt][0] += tanh_ap(c[mt][nt][0] + bia[nt][0]) + tanh_ap(c[mt][nt][2] + bia[nt][0]);
            csum[nt][1] += tanh_ap(c[mt][nt][1] + bia[nt][1]) + tanh_ap(c[mt][nt][3] + bia[nt][1]);
        }
    #pragma unroll
    for (int nt = 0; nt < 4; nt++)
        #pragma unroll
        for (int u = 0; u < 2; u++){
            float s = csum[nt][u];
            s += __shfl_xor_sync(0xffffffffu, s, 4);
            s += __shfl_xor_sync(0xffffffffu, s, 8);
            s += __shfl_xor_sync(0xffffffffu, s, 16);
            csum[nt][u] = s;
        }
    float* red = smem;
    if ((lane >> 2) == 0){
        #pragma unroll
        for (int nt = 0; nt < 4; nt++){
            int col = wn0 + (nt<<3) + ((lane&3)<<1);
            red[(warp&1)*128 + col]     = csum[nt][0];
            red[(warp&1)*128 + col + 1] = csum[nt][1];
        }
    }
    __syncthreads();
    if (tid < 128) Og[n0 + tid] = red[tid] + red[128 + tid];
}

// ---------------------------------------------------------------------------
__global__ void k_combine(float* __restrict__ out)
{
    const int idx = blockIdx.x * 256 + threadIdx.x;
    const int b = idx >> 9, h = idx & 511;
    float s = 0.f;
    #pragma unroll
    for (int w = 0; w < 2; w++)
        #pragma unroll
        for (int mb = 0; mb < 4; mb++)
            s += g_part[(size_t)((((w*NB) + b)<<2) + mb)*LD + h];
    out[idx] = s * (0.5f / 512.0f);
}

// ---------------------------------------------------------------------------
extern "C" void kernel_launch(void* const* d_in, const int* in_sizes, int n_in,
                              void* d_out, int out_size)
{
    (void)in_sizes; (void)n_in; (void)out_size;
    const float* I    = (const float*)d_in[0];
    const float* J    = (const float*)d_in[1];
    const float* W    = (const float*)d_in[2];
    const float* bias = (const float*)d_in[3];
    float* out = (float*)d_out;

    const int SM = 3*S2 + 256;
    cudaFuncSetAttribute(k_scores, cudaFuncAttributeMaxDynamicSharedMemorySize, SM);
    cudaFuncSetAttribute(k_wjwi,   cudaFuncAttributeMaxDynamicSharedMemorySize, SM);
    cudaFuncSetAttribute(k_agg,    cudaFuncAttributeMaxDynamicSharedMemorySize, SM);

    k_conv   <<<dim3(8,8,65), 256>>>(J, I, W);
    k_scores <<<dim3(4,4,NB),   256, SM>>>();
    k_finish <<<2*NBLD/256, 256>>>();
    k_wjwi   <<<dim3(4,4,2*NB), 256, SM>>>();
    k_agg    <<<dim3(16,NB,2),  256, SM>>>(bias);
    k_combine<<<64, 256>>>(out);
}